// round 7
// baseline (speedup 1.0000x reference)
#include <cuda_runtime.h>
#include <cuda_bf16.h>
#include <cstdint>

// PathRaster2d R6b: single kernel. 512 blocks, each owns a 4-row band (32KB
// static smem). Zero the band in smem, warp 0 draws any curve pixels falling
// in the band (full 32-sample min, arithmetic bit-identical to rounds 1-5,
// rel_err 0.0), then ONE cp.async.bulk (TMA engine) stores the whole band to
// GMEM. Store issue moves off the SM warps -> ~15 instrs/thread total.

#define CANVAS_H 2048
#define CANVAS_W 2048
#define NSAMP 32
#define BAND_ROWS 4
#define BAND_FLOATS (BAND_ROWS * CANVAS_W)        // 8192
#define BAND_BYTES  (BAND_FLOATS * 4)             // 32768
#define NTHREADS 256

__global__ void __launch_bounds__(NTHREADS)
path_raster_kernel(const float* __restrict__ kp, float* __restrict__ out)
{
    __shared__ float band[BAND_FLOATS];           // 32KB static

    const int tid = threadIdx.x;
    const int r0  = blockIdx.x * BAND_ROWS;       // first row of this band

    // ---- zero the smem band: 8 x STS.128 per thread ----
    float4* s4 = reinterpret_cast<float4*>(band);
    const float4 z = make_float4(0.0f, 0.0f, 0.0f, 0.0f);
    #pragma unroll
    for (int i = 0; i < BAND_FLOATS / 4 / NTHREADS; i++)
        s4[tid + i * NTHREADS] = z;
    __syncthreads();

    // ---- warp 0: samples + draw (reference-matched fp32 rounding) ----
    if (tid < 32) {
        // t_i = i * fl(1/31), endpoint forced to 1.0 (matches jnp.linspace)
        float t = (tid == 31) ? 1.0f : (float)tid * (1.0f / 31.0f);
        float u = __fsub_rn(1.0f, t);
        float b0 = __fmul_rn(u, u);
        float b1 = __fmul_rn(__fmul_rn(2.0f, t), u);
        float b2 = __fmul_rn(t, t);
        float ky0 = __fmul_rn(__ldg(kp + 0), 2048.0f), kx0 = __fmul_rn(__ldg(kp + 1), 2048.0f);
        float ky1 = __fmul_rn(__ldg(kp + 2), 2048.0f), kx1 = __fmul_rn(__ldg(kp + 3), 2048.0f);
        float ky2 = __fmul_rn(__ldg(kp + 4), 2048.0f), kx2 = __fmul_rn(__ldg(kp + 5), 2048.0f);
        float py = __fadd_rn(__fadd_rn(__fmul_rn(b0, ky0), __fmul_rn(b1, ky1)),
                             __fmul_rn(b2, ky2));
        float px = __fadd_rn(__fadd_rn(__fmul_rn(b0, kx0), __fmul_rn(b1, kx1)),
                             __fmul_rn(b2, kx2));

        const float maxd = sqrtf(2048.0f * 2048.0f + 2048.0f * 2048.0f);

        // For each sample whose +/-3 box intersects this band, evaluate the
        // full min for the box pixels. Any nonzero pixel is within 2px of its
        // argmin sample (|dy|<2, |dx|<2), hence inside that sample's 8x8 box,
        // and is handled by the block owning its row. Overlapping boxes
        // produce identical values (each computes the full 32-sample min).
        for (int s = 0; s < NSAMP; s++) {
            float psy = __shfl_sync(0xffffffffu, py, s);
            float psx = __shfl_sync(0xffffffffu, px, s);
            int iy0 = (int)floorf(psy) - 3;
            int ix0 = (int)floorf(psx) - 3;
            if (iy0 > r0 + BAND_ROWS - 1 || iy0 + 7 < r0) continue;  // warp-uniform
            #pragma unroll
            for (int h = 0; h < 2; h++) {
                int p  = tid + h * 32;               // 0..63 box pixel index
                int yq = iy0 + (p >> 3);
                int xq = ix0 + (p & 7);
                bool valid = (yq >= r0) && (yq < r0 + BAND_ROWS) &&
                             (xq >= 0) && (xq < CANVAS_W);
                float fy = (float)yq;
                float fx = (float)xq;
                float m = 3.4e38f;
                #pragma unroll
                for (int j = 0; j < NSAMP; j++) {    // all lanes run: shfl safe
                    float syv = __shfl_sync(0xffffffffu, py, j);
                    float sxv = __shfl_sync(0xffffffffu, px, j);
                    float dy  = __fsub_rn(fy, syv);
                    float dy2 = __fmul_rn(dy, dy);   // separate op, matches ref
                    float dx  = __fsub_rn(fx, sxv);
                    m = fminf(m, __fadd_rn(dy2, __fmul_rn(dx, dx)));
                }
                float d = sqrtf(m);                  // sqrt BEFORE compare
                if (valid && d < 2.0f)
                    band[(yq - r0) * CANVAS_W + xq] =
                        __fsub_rn(1.0f, __fdiv_rn(d, maxd));
            }
        }
    }
    __syncthreads();

    // ---- one bulk-async store of the whole band (TMA engine) ----
    if (tid == 0) {
        asm volatile("fence.proxy.async.shared::cta;" ::: "memory");
        unsigned int saddr;
        asm("{ .reg .u64 t; cvta.to.shared.u64 t, %1; cvt.u32.u64 %0, t; }"
            : "=r"(saddr) : "l"(band));
        float* gdst = out + (size_t)r0 * CANVAS_W;
        asm volatile("cp.async.bulk.global.shared::cta.bulk_group [%0], [%1], %2;"
                     :: "l"(gdst), "r"(saddr), "n"(BAND_BYTES) : "memory");
        asm volatile("cp.async.bulk.commit_group;" ::: "memory");
        asm volatile("cp.async.bulk.wait_group 0;" ::: "memory");
    }
}

extern "C" void kernel_launch(void* const* d_in, const int* in_sizes, int n_in,
                              void* d_out, int out_size)
{
    const float* kp = (const float*)d_in[0];   // [3,2] normalized (y,x)
    float* out = (float*)d_out;                // [2048,2048] fp32

    path_raster_kernel<<<CANVAS_H / BAND_ROWS, NTHREADS>>>(kp, out);  // 512 blocks
}

// round 8
// speedup vs baseline: 1.2316x; 1.2316x over previous
#include <cuda_runtime.h>
#include <cuda_bf16.h>
#include <cstdint>

// PathRaster2d R8: zeros-first. 1024 blocks (128x32 tiles, best measured
// config), 256 threads. Every thread issues its 4 STG.128 zeros IMMEDIATELY
// (no dependency on the kp load), so the ~600-cycle kp DRAM/L2 latency and
// sample math hide under the store drain. Warp then computes the 32 samples
// (one per lane, reference-matched rounding), exact point-to-box prune vs the
// block tile, ballot; active warps (rare) recompute their 16 pixels with the
// full 32-sample min and overwrite (same thread, same address => program-
// ordered, final value wins). Arithmetic bit-identical to R2/R3 (rel_err 0.0).

#define CANVAS_H 2048
#define CANVAS_W 2048
#define TILE_W 128
#define TILE_H 32

__global__ void __launch_bounds__(256)
path_raster_kernel(const float* __restrict__ kp, float* __restrict__ out)
{
    const int tx = threadIdx.x;          // 0..31 (lane == sample index)
    const int ty = threadIdx.y;          // 0..7
    const int x0 = blockIdx.x * TILE_W;
    const int y0 = blockIdx.y * TILE_H;

    const int x = x0 + tx * 4;
    float* base = out + (size_t)(y0 + ty) * CANVAS_W + x;   // rows ty + 8r

    // ---- phase 1: unconditional zero stores, no input dependency ----
    const float4 z = make_float4(0.0f, 0.0f, 0.0f, 0.0f);
    #pragma unroll
    for (int r = 0; r < 4; r++)
        *reinterpret_cast<float4*>(base + (size_t)(r * 8) * CANVAS_W) = z;

    // ---- phase 2: samples (hidden under store drain), ref-matched rounding ----
    // t_i = i * fl(1/31), endpoint forced to 1.0 (matches jnp.linspace)
    float t = (tx == 31) ? 1.0f : (float)tx * (1.0f / 31.0f);
    float u = __fsub_rn(1.0f, t);
    float b0 = __fmul_rn(u, u);
    float b1 = __fmul_rn(__fmul_rn(2.0f, t), u);
    float b2 = __fmul_rn(t, t);
    float ky0 = __fmul_rn(__ldg(kp + 0), 2048.0f), kx0 = __fmul_rn(__ldg(kp + 1), 2048.0f);
    float ky1 = __fmul_rn(__ldg(kp + 2), 2048.0f), kx1 = __fmul_rn(__ldg(kp + 3), 2048.0f);
    float ky2 = __fmul_rn(__ldg(kp + 4), 2048.0f), kx2 = __fmul_rn(__ldg(kp + 5), 2048.0f);
    float py = __fadd_rn(__fadd_rn(__fmul_rn(b0, ky0), __fmul_rn(b1, ky1)),
                         __fmul_rn(b2, ky2));
    float px = __fadd_rn(__fadd_rn(__fmul_rn(b0, kx0), __fmul_rn(b1, kx1)),
                         __fmul_rn(b2, kx2));

    // Exact point-to-tile-box distance; squared threshold 4.5 (> 4.0) pads for
    // rounding — only ever KEEPS extra samples (dist(pixel,s) >= boxdist(s),
    // so a sample with boxdist >= 2 can never decide a nonzero pixel here).
    float bdy = fmaxf(fmaxf((float)y0 - py, py - (float)(y0 + TILE_H - 1)), 0.0f);
    float bdx = fmaxf(fmaxf((float)x0 - px, px - (float)(x0 + TILE_W - 1)), 0.0f);
    bool near = (bdy * bdy + bdx * bdx) < 4.5f;
    unsigned mask = __ballot_sync(0xffffffffu, near);

    if (mask == 0u) return;              // 99.9% of warps: done

    // ---- phase 3 (rare): full min for this thread's 16 pixels, overwrite ----
    const float maxd = sqrtf(2048.0f * 2048.0f + 2048.0f * 2048.0f);
    const float fx0 = (float)x;
    const float fx1 = fx0 + 1.0f;
    const float fx2 = fx0 + 2.0f;
    const float fx3 = fx0 + 3.0f;
    #pragma unroll
    for (int r = 0; r < 4; r++) {
        const float fy = (float)(y0 + ty + r * 8);
        float m0 = 3.4e38f, m1 = 3.4e38f, m2 = 3.4e38f, m3 = 3.4e38f;
        unsigned mm = mask;              // warp-uniform loop
        while (mm) {
            int lane = __ffs(mm) - 1;
            mm &= mm - 1u;
            float syv = __shfl_sync(0xffffffffu, py, lane);
            float sxv = __shfl_sync(0xffffffffu, px, lane);
            float dy  = __fsub_rn(fy, syv);
            float dy2 = __fmul_rn(dy, dy);   // separate op, matches reference
            float d;
            d = __fsub_rn(fx0, sxv); m0 = fminf(m0, __fadd_rn(dy2, __fmul_rn(d, d)));
            d = __fsub_rn(fx1, sxv); m1 = fminf(m1, __fadd_rn(dy2, __fmul_rn(d, d)));
            d = __fsub_rn(fx2, sxv); m2 = fminf(m2, __fadd_rn(dy2, __fmul_rn(d, d)));
            d = __fsub_rn(fx3, sxv); m3 = fminf(m3, __fadd_rn(dy2, __fmul_rn(d, d)));
        }
        // sqrt BEFORE compare (boundary rounding identical to reference)
        float d0 = sqrtf(m0), d1 = sqrtf(m1), d2s = sqrtf(m2), d3 = sqrtf(m3);
        float4 v;
        v.x = (d0  < 2.0f) ? __fsub_rn(1.0f, __fdiv_rn(d0,  maxd)) : 0.0f;
        v.y = (d1  < 2.0f) ? __fsub_rn(1.0f, __fdiv_rn(d1,  maxd)) : 0.0f;
        v.z = (d2s < 2.0f) ? __fsub_rn(1.0f, __fdiv_rn(d2s, maxd)) : 0.0f;
        v.w = (d3  < 2.0f) ? __fsub_rn(1.0f, __fdiv_rn(d3,  maxd)) : 0.0f;
        *reinterpret_cast<float4*>(base + (size_t)(r * 8) * CANVAS_W) = v;
    }
}

extern "C" void kernel_launch(void* const* d_in, const int* in_sizes, int n_in,
                              void* d_out, int out_size)
{
    const float* kp = (const float*)d_in[0];   // [3,2] normalized (y,x)
    float* out = (float*)d_out;                // [2048,2048] fp32

    dim3 block(32, 8);
    dim3 grid(CANVAS_W / TILE_W, CANVAS_H / TILE_H);  // (16, 64) = 1024 blocks
    path_raster_kernel<<<grid, block>>>(kp, out);
}